// round 11
// baseline (speedup 1.0000x reference)
#include <cuda_runtime.h>
#include <cuda_bf16.h>
#include <cstdint>

#define THREADS 512
#define MDIM 1024
#define CDIM 128
#define MIDD 64
#define TM 64
#define NTILES 16
#define SA 272                      /* row stride bytes (136 bf16) */

// ---- persistent smem byte offsets (108.75 KB total -> 2 CTAs/SM) ----
#define A_HI0   0                   /* 64*272 = 17408 each */
#define A_HI1   17408
#define A_LO0   34816
#define A_LO1   52224
#define B_HI    69632
#define B_LO    87040
#define SMASK   104448              /* 1024 floats */
#define SLGP0   108544              /* 64 x 4 floats */
#define SLGP1   109568
#define SBB     110592
#define SWL     110848
#define SRED    111104              /* 64 floats */
#define SMEM_TOTAL 111360
// end-phase aliases (A tiles dead after the loop)
#define PST     A_HI0               /* 16 x 128 floats = 8192 */
#define PPOOL   A_HI1               /* 16 x 16 floats */
#define SPOOL   A_LO0               /* 64 floats */

// sred: 0=mask count, 1..16 mask warp partials, 32..47 lsum per warp, 48=inv_l

__device__ __forceinline__ uint32_t smem_u32(const void* p) {
    uint32_t a;
    asm("{ .reg .u64 t; cvta.to.shared.u64 t, %1; cvt.u32.u64 %0, t; }" : "=r"(a) : "l"(p));
    return a;
}
#define LDSM4(r0, r1, r2, r3, addr) \
    asm volatile("ldmatrix.sync.aligned.m8n8.x4.shared.b16 {%0,%1,%2,%3}, [%4];" \
                 : "=r"(r0), "=r"(r1), "=r"(r2), "=r"(r3) : "r"(addr))

__device__ __forceinline__ void mma16816(float* d, uint32_t a0, uint32_t a1, uint32_t a2, uint32_t a3,
                                         uint32_t b0, uint32_t b1) {
    asm volatile("mma.sync.aligned.m16n8k16.row.col.f32.bf16.bf16.f32 "
                 "{%0,%1,%2,%3}, {%4,%5,%6,%7}, {%8,%9}, {%0,%1,%2,%3};"
                 : "+f"(d[0]), "+f"(d[1]), "+f"(d[2]), "+f"(d[3])
                 : "r"(a0), "r"(a1), "r"(a2), "r"(a3), "r"(b0), "r"(b1));
}

__device__ __forceinline__ void cvt_hilo(float4 v, uint2& hi, uint2& lo) {
    __nv_bfloat162 h01 = __floats2bfloat162_rn(v.x, v.y);
    __nv_bfloat162 h23 = __floats2bfloat162_rn(v.z, v.w);
    float r0 = v.x - __bfloat162float(h01.x);
    float r1 = v.y - __bfloat162float(h01.y);
    float r2 = v.z - __bfloat162float(h23.x);
    float r3 = v.w - __bfloat162float(h23.y);
    __nv_bfloat162 l01 = __floats2bfloat162_rn(r0, r1);
    __nv_bfloat162 l23 = __floats2bfloat162_rn(r2, r3);
    hi = make_uint2(*(uint32_t*)&h01, *(uint32_t*)&h23);
    lo = make_uint2(*(uint32_t*)&l01, *(uint32_t*)&l23);
}

__global__ void __launch_bounds__(THREADS, 2) scatt_hmma(
    const float* __restrict__ q, const float* __restrict__ kf,
    const int* __restrict__ msk, const float* __restrict__ v1,
    const float* __restrict__ v2g, const float* __restrict__ wb,
    const float* __restrict__ bb, const float* __restrict__ wl,
    const float* __restrict__ bl, const float* __restrict__ wl2,
    const float* __restrict__ bl2, float* __restrict__ out)
{
    extern __shared__ char smem[];
    float* smask = (float*)(smem + SMASK);
    float* sbb   = (float*)(smem + SBB);
    float* swl   = (float*)(smem + SWL);
    float* sred  = (float*)(smem + SRED);

    const int tid = threadIdx.x;
    const int wid = tid >> 5;
    const int lane = tid & 31;
    const int bh = blockIdx.x;
    const int b = bh >> 3;
    const int h = bh & 7;

    const float* qv  = q   + bh * CDIM;
    const float* kfp = kf  + (size_t)bh * MDIM * CDIM;
    const float* v2p = v2g + (size_t)bh * MDIM * CDIM;
    const float* wbh = wb  + h * CDIM * MIDD;
    const int*   mkp = msk + b * MDIM;

    const uint32_t smb = smem_u32(smem);

    // ---- build B hi/lo: qw[o][i] = q[i]*W[i][o] ----
    #pragma unroll
    for (int it = 0; it < 16; ++it) {
        int idx = tid + it * THREADS;
        int i = idx >> 6, o = idx & 63;
        float w = qv[i] * wbh[idx];
        __nv_bfloat16 hi = __float2bfloat16(w);
        __nv_bfloat16 lo = __float2bfloat16(w - __bfloat162float(hi));
        uint32_t off = (uint32_t)(o * SA + i * 2);
        *(__nv_bfloat16*)(smem + B_HI + off) = hi;
        *(__nv_bfloat16*)(smem + B_LO + off) = lo;
    }
    // ---- mask to smem + exact count ----
    {
        float cl = 0.f;
        #pragma unroll
        for (int m = tid; m < MDIM; m += THREADS) {
            float mv = (float)mkp[m];
            smask[m] = mv;
            cl += mv;
        }
        #pragma unroll
        for (int off = 16; off; off >>= 1) cl += __shfl_xor_sync(0xffffffffu, cl, off);
        if (lane == 0) sred[1 + wid] = cl;
    }
    if (tid < MIDD) { sbb[tid] = bb[h * MIDD + tid]; swl[tid] = wl[h * MIDD + tid]; }

    // ---- preload tile 0 ----
    #pragma unroll
    for (int it = 0; it < 4; ++it) {
        int idx = tid + it * THREADS;
        int row = idx >> 5, c4 = idx & 31;
        float4 v = *(const float4*)(kfp + (size_t)row * CDIM + c4 * 4);
        uint2 hi, lo;
        cvt_hilo(v, hi, lo);
        uint32_t off = (uint32_t)(row * SA + c4 * 8);
        *(uint2*)(smem + A_HI0 + off) = hi;
        *(uint2*)(smem + A_LO0 + off) = lo;
    }
    __syncthreads();

    // ---- warp tiling: rb = wid&3 (rows rb*16..+16), chh = wid>>2 (cols chh*16..+16) ----
    const int rb = wid & 3;
    const int chh = wid >> 2;
    const int seg = lane >> 3;
    const int lr = lane & 7;
    const uint32_t aoff = (uint32_t)((rb * 16 + (seg & 1) * 8 + lr) * SA + (seg >> 1) * 16);
    const uint32_t boff = (uint32_t)((chh * 16 + (seg >> 1) * 8 + lr) * SA + (seg & 1) * 16);
    const uint32_t bhib = smb + B_HI;
    const uint32_t blob = smb + B_LO;

    const float blv = bl[h];
    float pool[2][2];
    pool[0][0] = pool[0][1] = pool[1][0] = pool[1][1] = 0.f;
    float4 vacc = make_float4(0.f, 0.f, 0.f, 0.f);
    float lsum = 0.f;
    float Mrun = -3.0e38f;
    float pr[4];
    #pragma unroll
    for (int r = 0; r < 4; ++r) pr[r] = 0.f;
    // v2 rows for this warp within each tile: wid*4 .. +4, channels lane*4..+4
    const float* v2w = v2p + (size_t)(wid * 4) * CDIM + (lane << 2);

    for (int t = 0; t < NTILES; ++t) {
        const int p = t & 1;
        // prefetch next A tile into registers
        float4 fr[4];
        if (t + 1 < NTILES) {
            const int m0n = (t + 1) * TM;
            #pragma unroll
            for (int it = 0; it < 4; ++it) {
                int idx = tid + it * THREADS;
                int row = idx >> 5, c4 = idx & 31;
                fr[it] = *(const float4*)(kfp + (size_t)(m0n + row) * CDIM + c4 * 4);
            }
        }
        // ---- pipelined v2 accumulation for tile t-1 ----
        if (t > 0) {
            const float* vr = v2w + (size_t)(t - 1) * TM * CDIM;
            #pragma unroll
            for (int r = 0; r < 4; ++r) {
                float4 x = *(const float4*)(vr + r * CDIM);
                vacc.x = fmaf(pr[r], x.x, vacc.x);
                vacc.y = fmaf(pr[r], x.y, vacc.y);
                vacc.z = fmaf(pr[r], x.z, vacc.z);
                vacc.w = fmaf(pr[r], x.w, vacc.w);
            }
        }

        const uint32_t ahib = smb + (p ? A_HI1 : A_HI0);
        const uint32_t alob = smb + (p ? A_LO1 : A_LO0);

        float acc[2][4];
        #pragma unroll
        for (int nt = 0; nt < 2; ++nt)
            #pragma unroll
            for (int j = 0; j < 4; ++j) acc[nt][j] = 0.f;

        #pragma unroll
        for (int kc = 0; kc < 8; ++kc) {
            const uint32_t kb = kc * 32;
            uint32_t ah0, ah1, ah2, ah3, al0, al1, al2, al3;
            LDSM4(ah0, ah1, ah2, ah3, ahib + aoff + kb);
            LDSM4(al0, al1, al2, al3, alob + aoff + kb);
            uint32_t bh0, bh1, bh2, bh3, bl0, bl1, bl2, bl3;
            LDSM4(bh0, bh1, bh2, bh3, bhib + boff + kb);
            LDSM4(bl0, bl1, bl2, bl3, blob + boff + kb);
            mma16816(acc[0], ah0, ah1, ah2, ah3, bh0, bh1);
            mma16816(acc[1], ah0, ah1, ah2, ah3, bh2, bh3);
            mma16816(acc[0], al0, al1, al2, al3, bh0, bh1);
            mma16816(acc[1], al0, al1, al2, al3, bh2, bh3);
            mma16816(acc[0], ah0, ah1, ah2, ah3, bl0, bl1);
            mma16816(acc[1], ah0, ah1, ah2, ah3, bl2, bl3);
        }

        // ---- epilogue: bias+relu, pool partials, logit partials -> slgp[parity] ----
        {
            float* slgp = (float*)(smem + (p ? SLGP1 : SLGP0));
            const int r0 = lane >> 2;
            const int m0 = t * TM + rb * 16;
            const float mk0 = smask[m0 + r0];
            const float mk1 = smask[m0 + r0 + 8];
            float ls0 = 0.f, ls1 = 0.f;
            #pragma unroll
            for (int nt = 0; nt < 2; ++nt) {
                const int c = chh * 16 + nt * 8 + (lane & 3) * 2;
                const float b0 = sbb[c], b1 = sbb[c + 1];
                const float w0 = swl[c], w1 = swl[c + 1];
                float a00 = fmaxf(acc[nt][0] + b0, 0.f);
                float a01 = fmaxf(acc[nt][1] + b1, 0.f);
                float a10 = fmaxf(acc[nt][2] + b0, 0.f);
                float a11 = fmaxf(acc[nt][3] + b1, 0.f);
                pool[nt][0] = fmaf(a00, mk0, fmaf(a10, mk1, pool[nt][0]));
                pool[nt][1] = fmaf(a01, mk0, fmaf(a11, mk1, pool[nt][1]));
                ls0 = fmaf(a00, w0, fmaf(a01, w1, ls0));
                ls1 = fmaf(a10, w0, fmaf(a11, w1, ls1));
            }
            ls0 += __shfl_xor_sync(0xffffffffu, ls0, 1);
            ls0 += __shfl_xor_sync(0xffffffffu, ls0, 2);
            ls1 += __shfl_xor_sync(0xffffffffu, ls1, 1);
            ls1 += __shfl_xor_sync(0xffffffffu, ls1, 2);
            if ((lane & 3) == 0) {
                slgp[(rb * 16 + r0) * 4 + chh] = ls0;
                slgp[(rb * 16 + r0 + 8) * 4 + chh] = ls1;
            }
        }
        // STS prefetched A tile (other buffer)
        if (t + 1 < NTILES) {
            char* dh = smem + ((t + 1) & 1 ? A_HI1 : A_HI0);
            char* dl = smem + ((t + 1) & 1 ? A_LO1 : A_LO0);
            #pragma unroll
            for (int it = 0; it < 4; ++it) {
                int idx = tid + it * THREADS;
                int row = idx >> 5, c4 = idx & 31;
                uint2 hi, lo;
                cvt_hilo(fr[it], hi, lo);
                uint32_t off = (uint32_t)(row * SA + c4 * 8);
                *(uint2*)(dh + off) = hi;
                *(uint2*)(dl + off) = lo;
            }
        }
        __syncthreads();                                   // ONE sync per tile

        // ---- redundant per-warp softmax state update ----
        {
            const float* slgp = (const float*)(smem + (p ? SLGP1 : SLGP0));
            // lane handles rows 2*lane, 2*lane+1
            float4 g0 = *(const float4*)(slgp + lane * 8);
            float4 g1 = *(const float4*)(slgp + lane * 8 + 4);
            const int mbase = t * TM + lane * 2;
            float lg[2];
            float s0 = (g0.x + g0.y) + (g0.z + g0.w);
            float s1 = (g1.x + g1.y) + (g1.z + g1.w);
            lg[0] = (smask[mbase + 0] == 0.f) ? -1e9f : (s0 + blv);
            lg[1] = (smask[mbase + 1] == 0.f) ? -1e9f : (s1 + blv);
            float mx = fmaxf(lg[0], lg[1]);
            #pragma unroll
            for (int off = 16; off; off >>= 1) mx = fmaxf(mx, __shfl_xor_sync(0xffffffffu, mx, off));
            float Mn = fmaxf(Mrun, mx);
            float sc = expf(Mrun - Mn);
            Mrun = Mn;
            vacc.x *= sc; vacc.y *= sc; vacc.z *= sc; vacc.w *= sc;
            lsum *= sc;
            // this warp's 4 rows: wid*4 + r; source lane = (wid*4+r)>>1 = wid*2+(r>>1)
            #pragma unroll
            for (int r = 0; r < 4; ++r) {
                float lgr = __shfl_sync(0xffffffffu, lg[r & 1], wid * 2 + (r >> 1));
                pr[r] = expf(lgr - Mn);
                lsum += pr[r];
            }
        }
    }

    // ---- drain: v2 accumulation for the last tile ----
    {
        const float* vr = v2w + (size_t)(NTILES - 1) * TM * CDIM;
        #pragma unroll
        for (int r = 0; r < 4; ++r) {
            float4 x = *(const float4*)(vr + r * CDIM);
            vacc.x = fmaf(pr[r], x.x, vacc.x);
            vacc.y = fmaf(pr[r], x.y, vacc.y);
            vacc.z = fmaf(pr[r], x.z, vacc.z);
            vacc.w = fmaf(pr[r], x.w, vacc.w);
        }
    }
    __syncthreads();   // A tiles dead; safe to alias staging arrays

    float* pst   = (float*)(smem + PST);
    float* ppool = (float*)(smem + PPOOL);
    float* spool = (float*)(smem + SPOOL);

    // ---- stage v2 partials + lsum ----
    {
        float* d = pst + wid * 128 + (lane << 2);
        d[0] = vacc.x; d[1] = vacc.y; d[2] = vacc.z; d[3] = vacc.w;
        if (lane == 0) sred[32 + wid] = lsum;
    }
    // ---- pool: reduce over row-lanes, stage ----
    #pragma unroll
    for (int nt = 0; nt < 2; ++nt)
        #pragma unroll
        for (int j = 0; j < 2; ++j) {
            float pv = pool[nt][j];
            pv += __shfl_xor_sync(0xffffffffu, pv, 4);
            pv += __shfl_xor_sync(0xffffffffu, pv, 8);
            pv += __shfl_xor_sync(0xffffffffu, pv, 16);
            if (lane < 4) ppool[wid * 16 + nt * 8 + lane * 2 + j] = pv;
        }
    __syncthreads();
    if (tid < MIDD) {
        int o = tid, co = o >> 4, idx = o & 15;
        float s = 0.f;
        #pragma unroll
        for (int r = 0; r < 4; ++r) s += ppool[(co * 4 + r) * 16 + idx];
        spool[o] = s;
    }
    if (tid == 0) {
        float c = 0.f;
        #pragma unroll
        for (int w = 0; w < 16; ++w) c += sred[1 + w];
        sred[0] = c;
        float l = 0.f;
        #pragma unroll
        for (int w = 0; w < 16; ++w) l += sred[32 + w];
        sred[48] = 1.f / l;
    }
    __syncthreads();

    // ---- alpha_channel + final output ----
    if (tid < CDIM) {
        const int ch = tid;
        float v2c = 0.f;
        #pragma unroll
        for (int w = 0; w < 16; ++w) v2c += pst[w * 128 + ch];
        v2c *= sred[48];
        const float invc = 1.f / sred[0];
        float x = bl2[h * CDIM + ch];
        const float* w2 = wl2 + h * MIDD * CDIM + ch;
        #pragma unroll 8
        for (int o = 0; o < MIDD; ++o) x = fmaf(spool[o] * invc, w2[o * CDIM], x);
        float sig = 1.f / (1.f + expf(-x));
        out[bh * CDIM + ch] = v1[bh * CDIM + ch] * v2c * sig;
    }
}

extern "C" void kernel_launch(void* const* d_in, const int* in_sizes, int n_in,
                              void* d_out, int out_size) {
    const float* q   = (const float*)d_in[0];
    const float* kf  = (const float*)d_in[1];
    const int*   msk = (const int*)d_in[2];
    const float* v1  = (const float*)d_in[3];
    const float* v2  = (const float*)d_in[4];
    const float* wb  = (const float*)d_in[5];
    const float* bbp = (const float*)d_in[6];
    const float* wlp = (const float*)d_in[7];
    const float* blp = (const float*)d_in[8];
    const float* wl2 = (const float*)d_in[9];
    const float* bl2 = (const float*)d_in[10];
    float* out = (float*)d_out;

    cudaFuncSetAttribute(scatt_hmma, cudaFuncAttributeMaxDynamicSharedMemorySize, SMEM_TOTAL);
    scatt_hmma<<<512, THREADS, SMEM_TOTAL>>>(q, kf, msk, v1, v2, wb, bbp, wlp, blp, wl2, bl2, out);
}

// round 15
// speedup vs baseline: 1.1270x; 1.1270x over previous
#include <cuda_runtime.h>
#include <cuda_bf16.h>
#include <cstdint>

#define THREADS 256
#define MDIM 1024
#define CDIM 128
#define MIDD 64
#define TM 64
#define NTILES 16
#define SA 272                      /* row stride bytes (136 bf16) */

// ---- persistent smem byte offsets (111.7 KB -> 2 CTAs/SM) ----
#define A_HI0   0                   /* 64*272 = 17408 each */
#define A_HI1   17408
#define A_LO0   34816
#define A_LO1   52224
#define B_HI    69632
#define B_LO    87040
#define SMASK   104448              /* 1024 floats */
#define SLGP0   108544              /* 64 x 2 floats (parity 0) */
#define SLGP1   109056              /* 64 x 2 floats (parity 1) */
#define SBB     109568
#define SWL     109824
#define SRED    110080              /* 64 floats */
#define SMEM_TOTAL 110336
// end-phase aliases (A tiles dead after the main loop)
#define PST     A_HI0               /* 8 x 128 floats */
#define PPOOL   A_HI1               /* 8 x 32 floats */
#define SPOOL   A_LO0               /* 64 floats */

// sred: 0=mask count, 1..8 mask warp partials, 32..39 lsum per warp, 48=inv_l

__device__ __forceinline__ uint32_t smem_u32(const void* p) {
    uint32_t a;
    asm("{ .reg .u64 t; cvta.to.shared.u64 t, %1; cvt.u32.u64 %0, t; }" : "=r"(a) : "l"(p));
    return a;
}
#define LDSM4(r0, r1, r2, r3, addr) \
    asm volatile("ldmatrix.sync.aligned.m8n8.x4.shared.b16 {%0,%1,%2,%3}, [%4];" \
                 : "=r"(r0), "=r"(r1), "=r"(r2), "=r"(r3) : "r"(addr))

__device__ __forceinline__ void mma16816(float* d, uint32_t a0, uint32_t a1, uint32_t a2, uint32_t a3,
                                         uint32_t b0, uint32_t b1) {
    asm volatile("mma.sync.aligned.m16n8k16.row.col.f32.bf16.bf16.f32 "
                 "{%0,%1,%2,%3}, {%4,%5,%6,%7}, {%8,%9}, {%0,%1,%2,%3};"
                 : "+f"(d[0]), "+f"(d[1]), "+f"(d[2]), "+f"(d[3])
                 : "r"(a0), "r"(a1), "r"(a2), "r"(a3), "r"(b0), "r"(b1));
}

__device__ __forceinline__ void cvt_hilo(float4 v, uint2& hi, uint2& lo) {
    __nv_bfloat162 h01 = __floats2bfloat162_rn(v.x, v.y);
    __nv_bfloat162 h23 = __floats2bfloat162_rn(v.z, v.w);
    float r0 = v.x - __bfloat162float(h01.x);
    float r1 = v.y - __bfloat162float(h01.y);
    float r2 = v.z - __bfloat162float(h23.x);
    float r3 = v.w - __bfloat162float(h23.y);
    __nv_bfloat162 l01 = __floats2bfloat162_rn(r0, r1);
    __nv_bfloat162 l23 = __floats2bfloat162_rn(r2, r3);
    hi = make_uint2(*(uint32_t*)&h01, *(uint32_t*)&h23);
    lo = make_uint2(*(uint32_t*)&l01, *(uint32_t*)&l23);
}

__global__ void __launch_bounds__(THREADS, 2) scatt_hmma(
    const float* __restrict__ q, const float* __restrict__ kf,
    const int* __restrict__ msk, const float* __restrict__ v1,
    const float* __restrict__ v2g, const float* __restrict__ wb,
    const float* __restrict__ bb, const float* __restrict__ wl,
    const float* __restrict__ bl, const float* __restrict__ wl2,
    const float* __restrict__ bl2, float* __restrict__ out)
{
    extern __shared__ char smem[];
    float* smask = (float*)(smem + SMASK);
    float* sbb   = (float*)(smem + SBB);
    float* swl   = (float*)(smem + SWL);
    float* sred  = (float*)(smem + SRED);

    const int tid = threadIdx.x;
    const int wid = tid >> 5;
    const int lane = tid & 31;
    const int bh = blockIdx.x;
    const int b = bh >> 3;
    const int h = bh & 7;

    const float* qv  = q   + bh * CDIM;
    const float* kfp = kf  + (size_t)bh * MDIM * CDIM;
    const float* v2p = v2g + (size_t)bh * MDIM * CDIM;
    const float* wbh = wb  + h * CDIM * MIDD;
    const int*   mkp = msk + b * MDIM;

    const uint32_t smb = smem_u32(smem);

    // ---- build B hi/lo: qw[o][i] = q[i]*W[i][o] ----
    #pragma unroll 8
    for (int idx = tid; idx < CDIM * MIDD; idx += THREADS) {
        int i = idx >> 6, o = idx & 63;
        float w = qv[i] * wbh[idx];
        __nv_bfloat16 hi = __float2bfloat16(w);
        __nv_bfloat16 lo = __float2bfloat16(w - __bfloat162float(hi));
        uint32_t off = (uint32_t)(o * SA + i * 2);
        *(__nv_bfloat16*)(smem + B_HI + off) = hi;
        *(__nv_bfloat16*)(smem + B_LO + off) = lo;
    }
    // ---- mask to smem + exact count ----
    {
        float cl = 0.f;
        #pragma unroll
        for (int m = tid; m < MDIM; m += THREADS) {
            float mv = (float)mkp[m];
            smask[m] = mv;
            cl += mv;
        }
        #pragma unroll
        for (int off = 16; off; off >>= 1) cl += __shfl_xor_sync(0xffffffffu, cl, off);
        if (lane == 0) sred[1 + wid] = cl;
    }
    if (tid < MIDD) { sbb[tid] = bb[h * MIDD + tid]; swl[tid] = wl[h * MIDD + tid]; }

    // ---- preload tile 0 (64 rows x 32 f4 = 2048 elems / 256 thr = 8 iters) ----
    #pragma unroll
    for (int it = 0; it < 8; ++it) {
        int idx = tid + it * THREADS;
        int row = idx >> 5, c4 = idx & 31;
        float4 v = *(const float4*)(kfp + (size_t)row * CDIM + c4 * 4);
        uint2 hi, lo;
        cvt_hilo(v, hi, lo);
        uint32_t off = (uint32_t)(row * SA + c4 * 8);
        *(uint2*)(smem + A_HI0 + off) = hi;
        *(uint2*)(smem + A_LO0 + off) = lo;
    }
    __syncthreads();

    // ---- warp tiling: rb = wid&3 (rows rb*16..+16), chh = wid>>2 (cols chh*32..+32) ----
    const int rb = wid & 3;
    const int chh = wid >> 2;
    const int seg = lane >> 3;
    const int lr = lane & 7;
    const uint32_t aoff = (uint32_t)((rb * 16 + (seg & 1) * 8 + lr) * SA + (seg >> 1) * 16);
    const uint32_t boff0 = (uint32_t)((chh * 32 + (seg >> 1) * 8 + lr) * SA + (seg & 1) * 16);
    const uint32_t boff1 = (uint32_t)((chh * 32 + 16 + (seg >> 1) * 8 + lr) * SA + (seg & 1) * 16);
    const uint32_t bhib = smb + B_HI;
    const uint32_t blob = smb + B_LO;

    const float blv = bl[h];
    float pool[4][2];
    #pragma unroll
    for (int nt = 0; nt < 4; ++nt) { pool[nt][0] = 0.f; pool[nt][1] = 0.f; }
    float4 vacc = make_float4(0.f, 0.f, 0.f, 0.f);
    float lsum = 0.f;
    float Mrun = -3.0e38f;
    float pr[8];
    #pragma unroll
    for (int r = 0; r < 8; ++r) pr[r] = 0.f;
    // v2 rows for this warp within each tile: wid*8 .. +8, channels lane*4..+4
    const float* v2w = v2p + (size_t)(wid * 8) * CDIM + (lane << 2);

    for (int t = 0; t < NTILES; ++t) {
        const int p = t & 1;
        // prefetch next A tile into registers
        float4 fr[8];
        if (t + 1 < NTILES) {
            const int m0n = (t + 1) * TM;
            #pragma unroll
            for (int it = 0; it < 8; ++it) {
                int idx = tid + it * THREADS;
                int row = idx >> 5, c4 = idx & 31;
                fr[it] = *(const float4*)(kfp + (size_t)(m0n + row) * CDIM + c4 * 4);
            }
        }
        // ---- pipelined v2 accumulation for tile t-1 (pr in registers) ----
        if (t > 0) {
            const float* vr = v2w + (size_t)(t - 1) * TM * CDIM;
            #pragma unroll
            for (int r = 0; r < 8; ++r) {
                float4 x = *(const float4*)(vr + r * CDIM);
                vacc.x = fmaf(pr[r], x.x, vacc.x);
                vacc.y = fmaf(pr[r], x.y, vacc.y);
                vacc.z = fmaf(pr[r], x.z, vacc.z);
                vacc.w = fmaf(pr[r], x.w, vacc.w);
            }
        }

        const uint32_t ahib = smb + (p ? A_HI1 : A_HI0);
        const uint32_t alob = smb + (p ? A_LO1 : A_LO0);

        float acc[4][4];
        #pragma unroll
        for (int nt = 0; nt < 4; ++nt)
            #pragma unroll
            for (int j = 0; j < 4; ++j) acc[nt][j] = 0.f;

        #pragma unroll
        for (int kc = 0; kc < 8; ++kc) {
            const uint32_t kb = kc * 32;
            uint32_t ah0, ah1, ah2, ah3, al0, al1, al2, al3;
            LDSM4(ah0, ah1, ah2, ah3, ahib + aoff + kb);
            LDSM4(al0, al1, al2, al3, alob + aoff + kb);
            uint32_t bh0, bh1, bh2, bh3, bl0, bl1, bl2, bl3;
            LDSM4(bh0, bh1, bh2, bh3, bhib + boff0 + kb);
            LDSM4(bl0, bl1, bl2, bl3, blob + boff0 + kb);
            mma16816(acc[0], ah0, ah1, ah2, ah3, bh0, bh1);
            mma16816(acc[1], ah0, ah1, ah2, ah3, bh2, bh3);
            mma16816(acc[0], al0, al1, al2, al3, bh0, bh1);
            mma16816(acc[1], al0, al1, al2, al3, bh2, bh3);
            mma16816(acc[0], ah0, ah1, ah2, ah3, bl0, bl1);
            mma16816(acc[1], ah0, ah1, ah2, ah3, bl2, bl3);
            LDSM4(bh0, bh1, bh2, bh3, bhib + boff1 + kb);
            LDSM4(bl0, bl1, bl2, bl3, blob + boff1 + kb);
            mma16816(acc[2], ah0, ah1, ah2, ah3, bh0, bh1);
            mma16816(acc[3], ah0, ah1, ah2, ah3, bh2, bh3);
            mma16816(acc[2], al0, al1, al2, al3, bh0, bh1);
            mma16816(acc[3], al0, al1, al2, al3, bh2, bh3);
            mma16816(acc[2], ah0, ah1, ah2, ah3, bl0, bl1);
            mma16816(acc[3], ah0, ah1, ah2, ah3, bl2, bl3);
        }

        // ---- epilogue: bias+relu, pool partials, logit partials -> slgp[parity] ----
        {
            float* slgp = (float*)(smem + (p ? SLGP1 : SLGP0));
            const int r0 = lane >> 2;
            const int m0 = t * TM + rb * 16;
            const float mk0 = smask[m0 + r0];
            const float mk1 = smask[m0 + r0 + 8];
            float ls0 = 0.f, ls1 = 0.f;
            #pragma unroll
            for (int nt = 0; nt < 4; ++nt) {
                const int c = chh * 32 + nt * 8 + (lane & 3) * 2;
                const float b0 = sbb[c], b1 = sbb[c + 1];
                const float w0 = swl[c], w1 = swl[c + 1];
                float a00 = fmaxf(acc[nt][0] + b0, 0.f);
                float a01 = fmaxf(acc[nt][1] + b1, 0.f);
                float a10 = fmaxf(acc[nt][2] + b0, 0.f);
                float a11 = fmaxf(acc[nt][3] + b1, 0.f);
                pool[nt][0] = fmaf(a00, mk0, fmaf(a10, mk1, pool[nt][0]));
                pool[nt][1] = fmaf(a01, mk0, fmaf(a11, mk1, pool[nt][1]));
                ls0 = fmaf(a00, w0, fmaf(a01, w1, ls0));
                ls1 = fmaf(a10, w0, fmaf(a11, w1, ls1));
            }
            ls0 += __shfl_xor_sync(0xffffffffu, ls0, 1);
            ls0 += __shfl_xor_sync(0xffffffffu, ls0, 2);
            ls1 += __shfl_xor_sync(0xffffffffu, ls1, 1);
            ls1 += __shfl_xor_sync(0xffffffffu, ls1, 2);
            if ((lane & 3) == 0) {
                slgp[(rb * 16 + r0) * 2 + chh] = ls0;
                slgp[(rb * 16 + r0 + 8) * 2 + chh] = ls1;
            }
        }
        // STS prefetched A tile (other buffer)
        if (t + 1 < NTILES) {
            char* dh = smem + ((t + 1) & 1 ? A_HI1 : A_HI0);
            char* dl = smem + ((t + 1) & 1 ? A_LO1 : A_LO0);
            #pragma unroll
            for (int it = 0; it < 8; ++it) {
                int idx = tid + it * THREADS;
                int row = idx >> 5, c4 = idx & 31;
                uint2 hi, lo;
                cvt_hilo(fr[it], hi, lo);
                uint32_t off = (uint32_t)(row * SA + c4 * 8);
                *(uint2*)(dh + off) = hi;
                *(uint2*)(dl + off) = lo;
            }
        }
        __syncthreads();                                   // ONE sync per tile

        // ---- redundant per-warp softmax state update ----
        {
            const float* slgp = (const float*)(smem + (p ? SLGP1 : SLGP0));
            // lane handles rows 2*lane, 2*lane+1 (one float4 covers both)
            float4 g = *(const float4*)(slgp + lane * 4);
            const int mbase = t * TM + lane * 2;
            float lg[2];
            lg[0] = (smask[mbase + 0] == 0.f) ? -1e9f : (g.x + g.y + blv);
            lg[1] = (smask[mbase + 1] == 0.f) ? -1e9f : (g.z + g.w + blv);
            float mx = fmaxf(lg[0], lg[1]);
            #pragma unroll
            for (int off = 16; off; off >>= 1) mx = fmaxf(mx, __shfl_xor_sync(0xffffffffu, mx, off));
            float Mn = fmaxf(Mrun, mx);
            float sc = expf(Mrun - Mn);
            Mrun = Mn;
            vacc.x *= sc; vacc.y *= sc; vacc.z *= sc; vacc.w *= sc;
            lsum *= sc;
            // this warp's 8 rows: wid*8 + r; source lane = wid*4 + (r>>1), slot r&1
            #pragma unroll
            for (int r = 0; r < 8; ++r) {
                float lgr = __shfl_sync(0xffffffffu, lg[r & 1], wid * 4 + (r >> 1));
                pr[r] = expf(lgr - Mn);
                lsum += pr[r];
            }
        }
    }

    // ---- drain: v2 accumulation for the last tile ----
    {
        const float* vr = v2w + (size_t)(NTILES - 1) * TM * CDIM;
        #pragma unroll
        for (int r = 0; r < 8; ++r) {
            float4 x = *(const float4*)(vr + r * CDIM);
            vacc.x = fmaf(pr[r], x.x, vacc.x);
            vacc.y = fmaf(pr[r], x.y, vacc.y);
            vacc.z = fmaf(pr[r], x.z, vacc.z);
            vacc.w = fmaf(pr[r], x.w, vacc.w);
        }
    }
    __syncthreads();   // A tiles dead; safe to alias staging arrays

    float* pst   = (float*)(smem + PST);
    float* ppool = (float*)(smem + PPOOL);
    float* spool = (float*)(smem + SPOOL);

    // ---- stage v2 partials + lsum (lsum identical across lanes of a warp) ----
    {
        float* d = pst + wid * 128 + (lane << 2);
        d[0] = vacc.x; d[1] = vacc.y; d[2] = vacc.z; d[3] = vacc.w;
        if (lane == 0) sred[32 + wid] = lsum;
    }
    // ---- pool: reduce over row-lanes, stage ----
    #pragma unroll
    for (int nt = 0; nt < 4; ++nt)
        #pragma unroll
        for (int j = 0; j < 2; ++j) {
            float pv = pool[nt][j];
            pv += __shfl_xor_sync(0xffffffffu, pv, 4);
            pv += __shfl_xor_sync(0xffffffffu, pv, 8);
            pv += __shfl_xor_sync(0xffffffffu, pv, 16);
            if (lane < 4) ppool[wid * 32 + nt * 8 + lane * 2 + j] = pv;
        }
    __syncthreads();
    if (tid < MIDD) {
        int o = tid, ch = o >> 5;
        float s = 0.f;
        #pragma unroll
        for (int r = 0; r < 4; ++r) s += ppool[(ch * 4 + r) * 32 + (o & 31)];
        spool[o] = s;
    }
    if (tid == 0) {
        float c = 0.f;
        #pragma unroll
        for (int w = 0; w < 8; ++w) c += sred[1 + w];
        sred[0] = c;
        float l = 0.f;
        #pragma unroll
        for (int w = 0; w < 8; ++w) l += sred[32 + w];
        sred[48] = 1.f / l;
    }
    __syncthreads();

    // ---- alpha_channel + final output ----
    if (tid < CDIM) {
        const int ch = tid;
        float v2c = 0.f;
        #pragma unroll
        for (int w = 0; w < 8; ++w) v2c += pst[w * 128 + ch];
        v2c *= sred[48];
        const float invc = 1.f / sred[0];
        float x = bl2[h * CDIM + ch];
        const float* w2 = wl2 + h * MIDD * CDIM + ch;
        #pragma unroll 8
        for (int o = 0; o < MIDD; ++o) x = fmaf(spool[o] * invc, w2[o * CDIM], x);
        float sig = 1.f / (1.f + expf(-x));
        out[bh * CDIM + ch] = v1[bh * CDIM + ch] * v2c * sig;
    }
}

extern "C" void kernel_launch(void* const* d_in, const int* in_sizes, int n_in,
                              void* d_out, int out_size) {
    const float* q   = (const float*)d_in[0];
    const float* kf  = (const float*)d_in[1];
    const int*   msk = (const int*)d_in[2];
    const float* v1  = (const float*)d_in[3];
    const float* v2  = (const float*)d_in[4];
    const float* wb  = (const float*)d_in[5];
    const float* bbp = (const float*)d_in[6];
    const float* wlp = (const float*)d_in[7];
    const float* blp = (const float*)d_in[8];
    const float* wl2 = (const float*)d_in[9];
    const float* bl2 = (const float*)d_in[10];
    float* out = (float*)d_out;

    cudaFuncSetAttribute(scatt_hmma, cudaFuncAttributeMaxDynamicSharedMemorySize, SMEM_TOTAL);
    scatt_hmma<<<512, THREADS, SMEM_TOTAL>>>(q, kf, msk, v1, v2, wb, bbp, wlp, blp, wl2, bl2, out);
}